// round 5
// baseline (speedup 1.0000x reference)
#include <cuda_runtime.h>
#include <math.h>

#define NB   32
#define NC   512
#define NHW  1024
#define NOUT 256
#define EPSV 1e-5f

// Scratch (device globals; no allocation allowed in kernel_launch)
__device__ float g_tp[NB][2*NOUT][NC];      // rows [0,256): theta, [256,512): phi  (32 MB)
__device__ float g_u[NB][NOUT];
__device__ float g_v[NB][NOUT];
__device__ float g_xepart[NB][NC][8];       // partial hw-sums of relu(bn3(conv3)) per hw-tile
__device__ float g_contrib[NB][NC];

// ---------------------------------------------------------------------------
// K1: theta/phi fused GEMM.  TP[b,o,c] = relu(bn((W[o,:]·x[b,c,:]) + bias))
// A = concat(w1,w2) [512,1024] K-major; B = x[b] [512,1024] K-major (NT GEMM).
// 128x128 tile, BK=16, 256 threads, 8x8 per thread.
// ---------------------------------------------------------------------------
__global__ __launch_bounds__(256) void k_theta_phi(
    const float* __restrict__ x,
    const float* __restrict__ w1, const float* __restrict__ b1,
    const float* __restrict__ g1, const float* __restrict__ be1,
    const float* __restrict__ m1, const float* __restrict__ v1,
    const float* __restrict__ w2, const float* __restrict__ b2,
    const float* __restrict__ g2, const float* __restrict__ be2,
    const float* __restrict__ m2, const float* __restrict__ v2)
{
    const int b   = blockIdx.z;
    const int om0 = blockIdx.y * 128;   // output-row (o) tile
    const int cn0 = blockIdx.x * 128;   // output-col (c) tile

    __shared__ float As[16][132];
    __shared__ float Bs[16][132];

    const int tid = threadIdx.x;
    const int tx  = tid & 15;
    const int ty  = tid >> 4;

    float acc[8][8];
    #pragma unroll
    for (int i = 0; i < 8; i++)
        #pragma unroll
        for (int j = 0; j < 8; j++) acc[i][j] = 0.f;

    const float* xb = x + (size_t)b * NC * NHW;
    const int ar = tid >> 2;            // 0..63
    const int ac = (tid & 3) * 4;       // 0,4,8,12

    // om0 is a multiple of 128, so a block is entirely theta or entirely phi
    const float* wbase = (om0 < NOUT) ? (w1 + (size_t)om0 * NHW)
                                      : (w2 + (size_t)(om0 - NOUT) * NHW);

    for (int k0 = 0; k0 < NHW; k0 += 16) {
        #pragma unroll
        for (int rr = 0; rr < 2; rr++) {
            int r = ar + rr * 64;
            float4 va = *(const float4*)(wbase + (size_t)r * NHW + k0 + ac);
            As[ac+0][r] = va.x; As[ac+1][r] = va.y; As[ac+2][r] = va.z; As[ac+3][r] = va.w;
            float4 vb = *(const float4*)(xb + (size_t)(cn0 + r) * NHW + k0 + ac);
            Bs[ac+0][r] = vb.x; Bs[ac+1][r] = vb.y; Bs[ac+2][r] = vb.z; Bs[ac+3][r] = vb.w;
        }
        __syncthreads();
        #pragma unroll
        for (int k = 0; k < 16; k++) {
            float a[8], bv[8];
            float4 t0 = *(const float4*)&As[k][ty*8];
            float4 t1 = *(const float4*)&As[k][ty*8 + 4];
            a[0]=t0.x; a[1]=t0.y; a[2]=t0.z; a[3]=t0.w;
            a[4]=t1.x; a[5]=t1.y; a[6]=t1.z; a[7]=t1.w;
            float4 u0 = *(const float4*)&Bs[k][tx*8];
            float4 u1 = *(const float4*)&Bs[k][tx*8 + 4];
            bv[0]=u0.x; bv[1]=u0.y; bv[2]=u0.z; bv[3]=u0.w;
            bv[4]=u1.x; bv[5]=u1.y; bv[6]=u1.z; bv[7]=u1.w;
            #pragma unroll
            for (int i = 0; i < 8; i++)
                #pragma unroll
                for (int j = 0; j < 8; j++)
                    acc[i][j] += a[i] * bv[j];
        }
        __syncthreads();
    }

    // Epilogue: +bias, BN (eval), ReLU, store
    #pragma unroll
    for (int i = 0; i < 8; i++) {
        const int o = om0 + ty * 8 + i;
        float bias, mm, sc, bt;
        if (o < NOUT) {
            bias = b1[o]; mm = m1[o]; sc = g1[o] * rsqrtf(v1[o] + EPSV); bt = be1[o];
        } else {
            int oo = o - NOUT;
            bias = b2[oo]; mm = m2[oo]; sc = g2[oo] * rsqrtf(v2[oo] + EPSV); bt = be2[oo];
        }
        float* dst = &g_tp[b][o][cn0 + tx * 8];
        #pragma unroll
        for (int j = 0; j < 8; j++) {
            float y = acc[i][j] + bias;
            y = (y - mm) * sc + bt;
            dst[j] = fmaxf(y, 0.f);
        }
    }
}

// ---------------------------------------------------------------------------
// K2: u[b,k] = Σ_c w4[1+c]·phi[b,k,c],  v[b,k] = Σ_c w4[1+NC+c]·theta[b,k,c]
// ---------------------------------------------------------------------------
__global__ __launch_bounds__(128) void k_uv(const float* __restrict__ w4)
{
    const int k = blockIdx.x, b = blockIdx.y;
    const int t = threadIdx.x;
    const float* phir = &g_tp[b][NOUT + k][0];
    const float* ther = &g_tp[b][k][0];
    float su = 0.f, sv = 0.f;
    for (int c = t; c < NC; c += 128) {
        su += w4[1 + c]      * phir[c];
        sv += w4[1 + NC + c] * ther[c];
    }
    #pragma unroll
    for (int o = 16; o > 0; o >>= 1) {
        su += __shfl_down_sync(0xffffffffu, su, o);
        sv += __shfl_down_sync(0xffffffffu, sv, o);
    }
    __shared__ float ssu[4], ssv[4];
    const int w = t >> 5;
    if ((t & 31) == 0) { ssu[w] = su; ssv[w] = sv; }
    __syncthreads();
    if (t == 0) {
        g_u[b][k] = ssu[0] + ssu[1] + ssu[2] + ssu[3];
        g_v[b][k] = ssv[0] + ssv[1] + ssv[2] + ssv[3];
    }
}

// ---------------------------------------------------------------------------
// K3: contrib[b,p] = Σ_k u[b,k]·theta[b,k,p] + v[b,k]·phi[b,k,p]
// ---------------------------------------------------------------------------
__global__ __launch_bounds__(128) void k_contrib()
{
    const int b = blockIdx.y;
    const int p = blockIdx.x * 128 + threadIdx.x;
    __shared__ float su[NOUT], sv[NOUT];
    for (int i = threadIdx.x; i < NOUT; i += 128) { su[i] = g_u[b][i]; sv[i] = g_v[b][i]; }
    __syncthreads();
    float acc = 0.f;
    #pragma unroll 8
    for (int k = 0; k < NOUT; k++)
        acc += su[k] * g_tp[b][k][p] + sv[k] * g_tp[b][NOUT + k][p];
    g_contrib[b][p] = acc;
}

// ---------------------------------------------------------------------------
// K4: fused conv3 GEMM + BN + ReLU + partial pool over hw.
// z[b,o,hw] = Σ_c w3[o,c]·x[b,c,hw] + b3[o];  partial[b,o,tile] = Σ_hw∈tile relu(bn3(z))
// 128(o) x 128(hw) tile, BK=16 over c.
// ---------------------------------------------------------------------------
__global__ __launch_bounds__(256) void k_xe(
    const float* __restrict__ x,
    const float* __restrict__ w3, const float* __restrict__ b3,
    const float* __restrict__ g3, const float* __restrict__ be3,
    const float* __restrict__ m3, const float* __restrict__ v3)
{
    const int b   = blockIdx.z;
    const int om0 = blockIdx.y * 128;   // o tile
    const int n0  = blockIdx.x * 128;   // hw tile

    __shared__ float As[16][132];
    __shared__ float Bs[16][128];
    __shared__ float red[128][17];

    const int tid = threadIdx.x;
    const int tx  = tid & 15;
    const int ty  = tid >> 4;

    float acc[8][8];
    #pragma unroll
    for (int i = 0; i < 8; i++)
        #pragma unroll
        for (int j = 0; j < 8; j++) acc[i][j] = 0.f;

    const float* xb = x + (size_t)b * NC * NHW;
    const int ar = tid >> 2,  ac = (tid & 3) * 4;    // A loader
    const int br = tid >> 5,  bc = (tid & 31) * 4;   // B loader

    for (int k0 = 0; k0 < NC; k0 += 16) {
        #pragma unroll
        for (int rr = 0; rr < 2; rr++) {
            int r = ar + rr * 64;
            float4 va = *(const float4*)(w3 + (size_t)(om0 + r) * NC + k0 + ac);
            As[ac+0][r] = va.x; As[ac+1][r] = va.y; As[ac+2][r] = va.z; As[ac+3][r] = va.w;
        }
        #pragma unroll
        for (int rr = 0; rr < 2; rr++) {
            int r = br + rr * 8;
            float4 vb = *(const float4*)(xb + (size_t)(k0 + r) * NHW + n0 + bc);
            *(float4*)&Bs[r][bc] = vb;
        }
        __syncthreads();
        #pragma unroll
        for (int k = 0; k < 16; k++) {
            float a[8], bv[8];
            float4 t0 = *(const float4*)&As[k][ty*8];
            float4 t1 = *(const float4*)&As[k][ty*8 + 4];
            a[0]=t0.x; a[1]=t0.y; a[2]=t0.z; a[3]=t0.w;
            a[4]=t1.x; a[5]=t1.y; a[6]=t1.z; a[7]=t1.w;
            float4 u0 = *(const float4*)&Bs[k][tx*8];
            float4 u1 = *(const float4*)&Bs[k][tx*8 + 4];
            bv[0]=u0.x; bv[1]=u0.y; bv[2]=u0.z; bv[3]=u0.w;
            bv[4]=u1.x; bv[5]=u1.y; bv[6]=u1.z; bv[7]=u1.w;
            #pragma unroll
            for (int i = 0; i < 8; i++)
                #pragma unroll
                for (int j = 0; j < 8; j++)
                    acc[i][j] += a[i] * bv[j];
        }
        __syncthreads();
    }

    // BN + ReLU + row-partial-sum over this hw tile
    #pragma unroll
    for (int i = 0; i < 8; i++) {
        const int o = om0 + ty * 8 + i;
        const float sc = g3[o] * rsqrtf(v3[o] + EPSV);
        const float bias = b3[o], mm = m3[o], bt = be3[o];
        float rs = 0.f;
        #pragma unroll
        for (int j = 0; j < 8; j++) {
            float y = acc[i][j] + bias;
            y = (y - mm) * sc + bt;
            rs += fmaxf(y, 0.f);
        }
        red[ty * 8 + i][tx] = rs;
    }
    __syncthreads();
    if (tid < 128) {
        float s = 0.f;
        #pragma unroll
        for (int j = 0; j < 16; j++) s += red[tid][j];
        g_xepart[b][om0 + tid][blockIdx.x] = s;   // one writer per slot: deterministic
    }
}

// ---------------------------------------------------------------------------
// K5: logits -> sigmoid -> out = x * gate  (one block per (b,p) row)
// ---------------------------------------------------------------------------
__global__ __launch_bounds__(256) void k_final(
    const float* __restrict__ x, const float* __restrict__ w4,
    const float* __restrict__ b4, float* __restrict__ out)
{
    const int bp = blockIdx.x;
    const int b = bp >> 9, p = bp & 511;
    float s = 0.f;
    #pragma unroll
    for (int j = 0; j < 8; j++) s += g_xepart[b][p][j];
    const float xe = s * (1.f / 1024.f);
    const float logit = w4[0] * xe + g_contrib[b][p] + b4[0];
    const float gate = 1.f / (1.f + expf(-logit));
    const float4* xi = (const float4*)(x + (size_t)bp * NHW);
    float4*       oo = (float4*)(out + (size_t)bp * NHW);
    float4 v = xi[threadIdx.x];
    v.x *= gate; v.y *= gate; v.z *= gate; v.w *= gate;
    oo[threadIdx.x] = v;
}

// ---------------------------------------------------------------------------
extern "C" void kernel_launch(void* const* d_in, const int* in_sizes, int n_in,
                              void* d_out, int out_size)
{
    const float* x   = (const float*)d_in[0];
    const float* w1  = (const float*)d_in[1];
    const float* b1  = (const float*)d_in[2];
    const float* g1  = (const float*)d_in[3];
    const float* be1 = (const float*)d_in[4];
    const float* m1  = (const float*)d_in[5];
    const float* v1  = (const float*)d_in[6];
    const float* w2  = (const float*)d_in[7];
    const float* b2  = (const float*)d_in[8];
    const float* g2  = (const float*)d_in[9];
    const float* be2 = (const float*)d_in[10];
    const float* m2  = (const float*)d_in[11];
    const float* v2  = (const float*)d_in[12];
    const float* w3  = (const float*)d_in[13];
    const float* b3  = (const float*)d_in[14];
    const float* g3  = (const float*)d_in[15];
    const float* be3 = (const float*)d_in[16];
    const float* m3  = (const float*)d_in[17];
    const float* v3  = (const float*)d_in[18];
    const float* w4  = (const float*)d_in[19];
    const float* b4  = (const float*)d_in[20];
    float* out = (float*)d_out;

    k_theta_phi<<<dim3(4, 4, NB), 256>>>(x, w1, b1, g1, be1, m1, v1,
                                         w2, b2, g2, be2, m2, v2);
    k_uv<<<dim3(NOUT, NB), 128>>>(w4);
    k_contrib<<<dim3(4, NB), 128>>>();
    k_xe<<<dim3(8, 4, NB), 256>>>(x, w3, b3, g3, be3, m3, v3);
    k_final<<<NB * NC, 256>>>(x, w4, b4, out);
}

// round 8
// speedup vs baseline: 2.4004x; 2.4004x over previous
#include <cuda_runtime.h>
#include <math.h>
#include <stdint.h>

#define NB   32
#define NC   512
#define NHW  1024
#define NOUT 256
#define EPSV 1e-5f
#define BKF  32                 // K floats per stage
#define ROWP 36                 // padded SMEM row stride (floats)
#define TILE_F (128 * ROWP)     // floats per 128xBKF buffer
#define SMEM_BYTES (4 * TILE_F * 4)   // A0,A1,B0,B1 = 73728 B

// Scratch (device globals; no allocation allowed in kernel_launch)
__device__ float g_tp[NB][2*NOUT][NC];      // theta rows [0,256), phi rows [256,512)
__device__ float g_xT[NB][NHW][NC];         // x transposed: [b][hw][c]
__device__ float g_u[NB][NOUT];
__device__ float g_v[NB][NOUT];
__device__ float g_xepart[NB][NC][32];      // 8 hw-tiles x 4 n-warps partial pools
__device__ float g_contrib[NB][NC];

extern __shared__ float dynf[];

// ------------------------- portable PTX helpers ----------------------------
__device__ __forceinline__ uint32_t smem_u32(const void* p) {
    uint32_t a;
    asm("{ .reg .u64 t; cvta.to.shared.u64 t, %1; cvt.u32.u64 %0, t; }" : "=r"(a) : "l"(p));
    return a;
}
__device__ __forceinline__ void cpa16(uint32_t dst, const void* src) {
    asm volatile("cp.async.cg.shared.global [%0], [%1], 16;" :: "r"(dst), "l"(src));
}
__device__ __forceinline__ void cpa_commit() { asm volatile("cp.async.commit_group;"); }
template<int N> __device__ __forceinline__ void cpa_wait() {
    asm volatile("cp.async.wait_group %0;" :: "n"(N));
}
__device__ __forceinline__ uint32_t tf32r(float x) {
    uint32_t u; asm("cvt.rna.tf32.f32 %0, %1;" : "=r"(u) : "f"(x)); return u;
}
__device__ __forceinline__ void mma8(float* c, const uint32_t* a, const uint32_t* b) {
    asm volatile("mma.sync.aligned.m16n8k8.row.col.f32.tf32.tf32.f32 "
        "{%0,%1,%2,%3}, {%4,%5,%6,%7}, {%8,%9}, {%0,%1,%2,%3};"
        : "+f"(c[0]), "+f"(c[1]), "+f"(c[2]), "+f"(c[3])
        : "r"(a[0]), "r"(a[1]), "r"(a[2]), "r"(a[3]), "r"(b[0]), "r"(b[1]));
}

// Async-copy a 128 x 32-float tile (row stride ld) into padded SMEM buffer.
__device__ __forceinline__ void load_tile_async(uint32_t sb, int dstf,
        const float* __restrict__ src, int ld, int k0, int tid) {
    #pragma unroll
    for (int i = 0; i < 4; i++) {
        const int c   = tid + i * 256;      // 0..1023 chunks of 16B
        const int row = c >> 3;
        const int off = (c & 7) * 4;
        cpa16(sb + (uint32_t)(dstf + row * ROWP + off) * 4u,
              src + (size_t)row * ld + k0 + off);
    }
}

// One BKF=32 stage of MMAs. Warp computes 64x32 via 4x4 m16n8k8 fragments.
__device__ __forceinline__ void stage_mma(const float* __restrict__ As,
                                          const float* __restrict__ Bs,
                                          int mb, int nb, int g, int tg,
                                          float (&acc)[4][4][4]) {
    #pragma unroll
    for (int ks = 0; ks < 4; ks++) {
        const int k8 = ks * 8;
        uint32_t bf[4][2];
        #pragma unroll
        for (int nf = 0; nf < 4; nf++) {
            const float* bp = Bs + (size_t)(nb + nf * 8 + g) * ROWP;
            bf[nf][0] = tf32r(bp[k8 + tg]);
            bf[nf][1] = tf32r(bp[k8 + 4 + tg]);
        }
        #pragma unroll
        for (int mf = 0; mf < 4; mf++) {
            const float* ap0 = As + (size_t)(mb + mf * 16 + g) * ROWP;
            const float* ap1 = ap0 + 8 * ROWP;
            uint32_t af[4];
            af[0] = tf32r(ap0[k8 + tg]);
            af[1] = tf32r(ap1[k8 + tg]);
            af[2] = tf32r(ap0[k8 + 4 + tg]);
            af[3] = tf32r(ap1[k8 + 4 + tg]);
            #pragma unroll
            for (int nf = 0; nf < 4; nf++) mma8(acc[mf][nf], af, bf[nf]);
        }
    }
}

// Double-buffered mainloop: D[128,128] += A[128,K] * B[128,K]^T (tf32, NT)
template<int KSTEPS>
__device__ __forceinline__ void gemm_main(uint32_t sb, float* sm,
        const float* __restrict__ A, int lda,
        const float* __restrict__ B, int ldb,
        int tid, int mb, int nb, int g, int tg, float (&acc)[4][4][4]) {
    load_tile_async(sb, 0,          A, lda, 0, tid);
    load_tile_async(sb, 2 * TILE_F, B, ldb, 0, tid);
    cpa_commit();
    for (int s = 0; s < KSTEPS; s++) {
        const int cur = s & 1;
        if (s + 1 < KSTEPS) {
            const int nxt = (s + 1) & 1;
            load_tile_async(sb, nxt * TILE_F,       A, lda, (s + 1) * BKF, tid);
            load_tile_async(sb, (2 + nxt) * TILE_F, B, ldb, (s + 1) * BKF, tid);
            cpa_commit();
            cpa_wait<1>();
        } else {
            cpa_wait<0>();
        }
        __syncthreads();
        stage_mma(sm + cur * TILE_F, sm + (2 + cur) * TILE_F, mb, nb, g, tg, acc);
        __syncthreads();
    }
}

// ---------------------------------------------------------------------------
// T0: transpose x[b][c][hw] -> g_xT[b][hw][c]
// ---------------------------------------------------------------------------
__global__ __launch_bounds__(256) void k_transpose(const float* __restrict__ x)
{
    __shared__ float t[32][33];
    const int b = blockIdx.z;
    const int c0 = blockIdx.y * 32, h0 = blockIdx.x * 32;
    const int tx = threadIdx.x & 31, ty = threadIdx.x >> 5;
    const float* xb = x + ((size_t)b * NC + c0) * NHW + h0;
    #pragma unroll
    for (int i = 0; i < 4; i++)
        t[ty + i * 8][tx] = xb[(size_t)(ty + i * 8) * NHW + tx];
    __syncthreads();
    float* ob = &g_xT[b][h0][c0];
    #pragma unroll
    for (int i = 0; i < 4; i++)
        ob[(size_t)(ty + i * 8) * NC + tx] = t[tx][ty + i * 8];
}

// ---------------------------------------------------------------------------
// K1: theta/phi GEMM via mma.sync tf32. grid (cn=4, om=4, b=32), 256 thr.
// ---------------------------------------------------------------------------
__global__ __launch_bounds__(256) void k_mma_tp(
    const float* __restrict__ x,
    const float* __restrict__ w1, const float* __restrict__ b1,
    const float* __restrict__ g1, const float* __restrict__ be1,
    const float* __restrict__ m1, const float* __restrict__ v1,
    const float* __restrict__ w2, const float* __restrict__ b2,
    const float* __restrict__ g2, const float* __restrict__ be2,
    const float* __restrict__ m2, const float* __restrict__ v2)
{
    float* sm = dynf;
    const uint32_t sb = smem_u32(sm);
    const int tid = threadIdx.x, lane = tid & 31, w = tid >> 5;
    const int mw = w & 1, nw = w >> 1;
    const int g = lane >> 2, tg = lane & 3;
    const int mb = mw * 64, nb = nw * 32;
    const int b = blockIdx.z, om0 = blockIdx.y * 128, cn0 = blockIdx.x * 128;

    float acc[4][4][4];
    #pragma unroll
    for (int i = 0; i < 4; i++)
        #pragma unroll
        for (int j = 0; j < 4; j++)
            #pragma unroll
            for (int q = 0; q < 4; q++) acc[i][j][q] = 0.f;

    const float* A = (om0 < NOUT) ? (w1 + (size_t)om0 * NHW)
                                  : (w2 + (size_t)(om0 - NOUT) * NHW);
    const float* B = x + ((size_t)b * NC + cn0) * NHW;

    gemm_main<NHW / BKF>(sb, sm, A, NHW, B, NHW, tid, mb, nb, g, tg, acc);

    // Epilogue: BN + ReLU, float2 stores
    #pragma unroll
    for (int mf = 0; mf < 4; mf++) {
        const int o0 = om0 + mb + mf * 16 + g;
        const int o1 = o0 + 8;
        float sc0, bp0, sc1, bp1;
        if (om0 < NOUT) {
            sc0 = g1[o0] * rsqrtf(v1[o0] + EPSV);
            bp0 = (b1[o0] - m1[o0]) * sc0 + be1[o0];
            sc1 = g1[o1] * rsqrtf(v1[o1] + EPSV);
            bp1 = (b1[o1] - m1[o1]) * sc1 + be1[o1];
        } else {
            const int p0 = o0 - NOUT, p1 = o1 - NOUT;
            sc0 = g2[p0] * rsqrtf(v2[p0] + EPSV);
            bp0 = (b2[p0] - m2[p0]) * sc0 + be2[p0];
            sc1 = g2[p1] * rsqrtf(v2[p1] + EPSV);
            bp1 = (b2[p1] - m2[p1]) * sc1 + be2[p1];
        }
        #pragma unroll
        for (int nf = 0; nf < 4; nf++) {
            const int col = cn0 + nb + nf * 8 + 2 * tg;
            float2 v0, v1_;
            v0.x  = fmaxf(acc[mf][nf][0] * sc0 + bp0, 0.f);
            v0.y  = fmaxf(acc[mf][nf][1] * sc0 + bp0, 0.f);
            v1_.x = fmaxf(acc[mf][nf][2] * sc1 + bp1, 0.f);
            v1_.y = fmaxf(acc[mf][nf][3] * sc1 + bp1, 0.f);
            *(float2*)&g_tp[b][o0][col] = v0;
            *(float2*)&g_tp[b][o1][col] = v1_;
        }
    }
}

// ---------------------------------------------------------------------------
// K4: conv3 GEMM + BN + ReLU + partial hw-pool. grid (hw=8, o=4, b=32).
// ---------------------------------------------------------------------------
__global__ __launch_bounds__(256) void k_mma_xe(
    const float* __restrict__ w3, const float* __restrict__ b3,
    const float* __restrict__ g3, const float* __restrict__ be3,
    const float* __restrict__ m3, const float* __restrict__ v3)
{
    float* sm = dynf;
    const uint32_t sb = smem_u32(sm);
    const int tid = threadIdx.x, lane = tid & 31, w = tid >> 5;
    const int mw = w & 1, nw = w >> 1;
    const int g = lane >> 2, tg = lane & 3;
    const int mb = mw * 64, nb = nw * 32;
    const int b = blockIdx.z, om0 = blockIdx.y * 128, n0 = blockIdx.x * 128;

    float acc[4][4][4];
    #pragma unroll
    for (int i = 0; i < 4; i++)
        #pragma unroll
        for (int j = 0; j < 4; j++)
            #pragma unroll
            for (int q = 0; q < 4; q++) acc[i][j][q] = 0.f;

    const float* A = w3 + (size_t)om0 * NC;
    const float* B = &g_xT[b][n0][0];

    gemm_main<NC / BKF>(sb, sm, A, NC, B, NC, tid, mb, nb, g, tg, acc);

    // Epilogue: BN + ReLU + row partial-sum over this warp's 32 hw columns
    #pragma unroll
    for (int mf = 0; mf < 4; mf++) {
        const int o0 = om0 + mb + mf * 16 + g;
        const int o1 = o0 + 8;
        const float sc0 = g3[o0] * rsqrtf(v3[o0] + EPSV);
        const float bp0 = (b3[o0] - m3[o0]) * sc0 + be3[o0];
        const float sc1 = g3[o1] * rsqrtf(v3[o1] + EPSV);
        const float bp1 = (b3[o1] - m3[o1]) * sc1 + be3[o1];
        float s0 = 0.f, s1 = 0.f;
        #pragma unroll
        for (int nf = 0; nf < 4; nf++) {
            s0 += fmaxf(acc[mf][nf][0] * sc0 + bp0, 0.f)
                + fmaxf(acc[mf][nf][1] * sc0 + bp0, 0.f);
            s1 += fmaxf(acc[mf][nf][2] * sc1 + bp1, 0.f)
                + fmaxf(acc[mf][nf][3] * sc1 + bp1, 0.f);
        }
        s0 += __shfl_xor_sync(0xffffffffu, s0, 1);
        s0 += __shfl_xor_sync(0xffffffffu, s0, 2);
        s1 += __shfl_xor_sync(0xffffffffu, s1, 1);
        s1 += __shfl_xor_sync(0xffffffffu, s1, 2);
        if (tg == 0) {
            g_xepart[b][o0][blockIdx.x * 4 + nw] = s0;
            g_xepart[b][o1][blockIdx.x * 4 + nw] = s1;
        }
    }
}

// ---------------------------------------------------------------------------
// K2: u[b,k] = Σ_c w4[1+c]·phi[b,k,c],  v[b,k] = Σ_c w4[1+NC+c]·theta[b,k,c]
// ---------------------------------------------------------------------------
__global__ __launch_bounds__(128) void k_uv(const float* __restrict__ w4)
{
    const int k = blockIdx.x, b = blockIdx.y;
    const int t = threadIdx.x;
    const float* phir = &g_tp[b][NOUT + k][0];
    const float* ther = &g_tp[b][k][0];
    float su = 0.f, sv = 0.f;
    for (int c = t; c < NC; c += 128) {
        su += w4[1 + c]      * phir[c];
        sv += w4[1 + NC + c] * ther[c];
    }
    #pragma unroll
    for (int o = 16; o > 0; o >>= 1) {
        su += __shfl_down_sync(0xffffffffu, su, o);
        sv += __shfl_down_sync(0xffffffffu, sv, o);
    }
    __shared__ float ssu[4], ssv[4];
    const int w = t >> 5;
    if ((t & 31) == 0) { ssu[w] = su; ssv[w] = sv; }
    __syncthreads();
    if (t == 0) {
        g_u[b][k] = ssu[0] + ssu[1] + ssu[2] + ssu[3];
        g_v[b][k] = ssv[0] + ssv[1] + ssv[2] + ssv[3];
    }
}

// ---------------------------------------------------------------------------
// K3: contrib[b,p] = Σ_k u[b,k]·theta[b,k,p] + v[b,k]·phi[b,k,p]
// ---------------------------------------------------------------------------
__global__ __launch_bounds__(128) void k_contrib()
{
    const int b = blockIdx.y;
    const int p = blockIdx.x * 128 + threadIdx.x;
    __shared__ float su[NOUT], sv[NOUT];
    for (int i = threadIdx.x; i < NOUT; i += 128) { su[i] = g_u[b][i]; sv[i] = g_v[b][i]; }
    __syncthreads();
    float acc = 0.f;
    #pragma unroll 8
    for (int k = 0; k < NOUT; k++)
        acc += su[k] * g_tp[b][k][p] + sv[k] * g_tp[b][NOUT + k][p];
    g_contrib[b][p] = acc;
}

// ---------------------------------------------------------------------------
// K5: logits -> sigmoid -> out = x * gate
// ---------------------------------------------------------------------------
__global__ __launch_bounds__(256) void k_final(
    const float* __restrict__ x, const float* __restrict__ w4,
    const float* __restrict__ b4, float* __restrict__ out)
{
    const int bp = blockIdx.x;
    const int b = bp >> 9, p = bp & 511;
    float s = 0.f;
    #pragma unroll
    for (int j = 0; j < 32; j++) s += g_xepart[b][p][j];
    const float xe = s * (1.f / 1024.f);
    const float logit = w4[0] * xe + g_contrib[b][p] + b4[0];
    const float gate = 1.f / (1.f + expf(-logit));
    const float4* xi = (const float4*)(x + (size_t)bp * NHW);
    float4*       oo = (float4*)(out + (size_t)bp * NHW);
    float4 v = xi[threadIdx.x];
    v.x *= gate; v.y *= gate; v.z *= gate; v.w *= gate;
    oo[threadIdx.x] = v;
}

// ---------------------------------------------------------------------------
extern "C" void kernel_launch(void* const* d_in, const int* in_sizes, int n_in,
                              void* d_out, int out_size)
{
    const float* x   = (const float*)d_in[0];
    const float* w1  = (const float*)d_in[1];
    const float* b1  = (const float*)d_in[2];
    const float* g1  = (const float*)d_in[3];
    const float* be1 = (const float*)d_in[4];
    const float* m1  = (const float*)d_in[5];
    const float* v1  = (const float*)d_in[6];
    const float* w2  = (const float*)d_in[7];
    const float* b2  = (const float*)d_in[8];
    const float* g2  = (const float*)d_in[9];
    const float* be2 = (const float*)d_in[10];
    const float* m2  = (const float*)d_in[11];
    const float* v2  = (const float*)d_in[12];
    const float* w3  = (const float*)d_in[13];
    const float* b3  = (const float*)d_in[14];
    const float* g3  = (const float*)d_in[15];
    const float* be3 = (const float*)d_in[16];
    const float* m3  = (const float*)d_in[17];
    const float* v3  = (const float*)d_in[18];
    const float* w4  = (const float*)d_in[19];
    const float* b4  = (const float*)d_in[20];
    float* out = (float*)d_out;

    cudaFuncSetAttribute(k_mma_tp, cudaFuncAttributeMaxDynamicSharedMemorySize, SMEM_BYTES);
    cudaFuncSetAttribute(k_mma_xe, cudaFuncAttributeMaxDynamicSharedMemorySize, SMEM_BYTES);

    k_transpose<<<dim3(32, 16, NB), 256>>>(x);
    k_mma_tp<<<dim3(4, 4, NB), 256, SMEM_BYTES>>>(x, w1, b1, g1, be1, m1, v1,
                                                  w2, b2, g2, be2, m2, v2);
    k_uv<<<dim3(NOUT, NB), 128>>>(w4);
    k_contrib<<<dim3(4, NB), 128>>>();
    k_mma_xe<<<dim3(8, 4, NB), 256, SMEM_BYTES>>>(w3, b3, g3, be3, m3, v3);
    k_final<<<NB * NC, 256>>>(x, w4, b4, out);
}